// round 15
// baseline (speedup 1.0000x reference)
#include <cuda_runtime.h>
#include <cuda_fp16.h>
#include <cstdint>

#define N_NODES 8192
#define INC 512
#define OUTC 256
#define ALPHA 0.5f
#define KSPLIT 1536                       // 3*INC for split-fp16 K1

// ---------------- scratch (device globals; no allocations allowed) ----------------
__device__ __half   g_WhT [OUTC * N_NODES];              // 4 MB fp16 Wh^T (K-major [n][k])
__device__ float    g_Wh1 [N_NODES];
__device__ float    g_Wh2 [N_NODES];
__device__ unsigned g_gmax2u;                            // max(Wh2) monotone uint key
__device__ float    g_srow[N_NODES];                     // softmax denominators
__device__ __half   g_h2  [(size_t)N_NODES * KSPLIT];    // 25 MB  [h_hi | h_lo | h_hi]
__device__ __half   g_W2T [OUTC * KSPLIT];               // 768 KB [n][k] = {W_hi;W_hi;W_lo}
__device__ __half   g_P   [(size_t)N_NODES * N_NODES];   // 128 MB unnormalized attention
__device__ float    g_part[2][N_NODES * OUTC];           // 16 MB k-split partials
__device__ float    g_pd  [2][2][N_NODES];               // [s1/s2][colCTA][row] dot partials
__device__ uint32_t g_bits[N_NODES * (N_NODES / 32)];    // 8 MB packed adj [row][word]

// ---- stream/events for k0 || k1-stack overlap; created at static-init ----
struct OverlapRes {
    cudaStream_t s0;
    cudaEvent_t  evFork, evK0;
    OverlapRes() {
        cudaStreamCreateWithFlags(&s0, cudaStreamNonBlocking);
        cudaEventCreateWithFlags(&evFork, cudaEventDisableTiming);
        cudaEventCreateWithFlags(&evK0,   cudaEventDisableTiming);
    }
};
static OverlapRes g_res;

__device__ __forceinline__ unsigned fkey(float x) {
    unsigned b = __float_as_uint(x);
    return (b & 0x80000000u) ? ~b : (b | 0x80000000u);
}
__device__ __forceinline__ float funkey(unsigned u) {
    unsigned b = (u & 0x80000000u) ? (u & 0x7FFFFFFFu) : ~u;
    return __uint_as_float(b);
}

// ================= K0: pack adj -> row-major bitmask g_bits[i][w] ======================
__global__ void __launch_bounds__(256) k0_pack(const int* __restrict__ adj) {
    int i = blockIdx.x;
    int t = threadIdx.x, wi = t >> 5, lane = t & 31;
    const int* row = adj + (size_t)i * N_NODES;
    #pragma unroll 8
    for (int k = 0; k < 32; k++) {
        int w = k * 8 + wi;
        int v = __ldcs(&row[w * 32 + lane]);
        unsigned m = __ballot_sync(0xffffffff, v > 0);
        if (lane == 0) g_bits[i * 256 + w] = m;
    }
}

// ================= K1a: split h -> [h_hi | h_lo | h_hi] fp16 ===========================
__global__ void __launch_bounds__(256) k1a_split(const float* __restrict__ hsrc) {
    if (blockIdx.x == 0 && threadIdx.x == 0) g_gmax2u = 0u;
    int idx = blockIdx.x * 256 + threadIdx.x;
    int i = idx >> 7, q = idx & 127;
    float4 v = *reinterpret_cast<const float4*>(hsrc + (size_t)idx * 4);
    __half hx = __float2half_rn(v.x), hy = __float2half_rn(v.y);
    __half hz = __float2half_rn(v.z), hw = __float2half_rn(v.w);
    __half lx = __float2half_rn(v.x - __half2float(hx));
    __half ly = __float2half_rn(v.y - __half2float(hy));
    __half lz = __float2half_rn(v.z - __half2float(hz));
    __half lw = __float2half_rn(v.w - __half2float(hw));
    __half2 hi01 = __halves2half2(hx, hy), hi23 = __halves2half2(hz, hw);
    __half2 lo01 = __halves2half2(lx, ly), lo23 = __halves2half2(lz, lw);
    __half* base = g_h2 + (size_t)i * KSPLIT + q * 4;
    *reinterpret_cast<__half2*>(base + 0) = hi01; *reinterpret_cast<__half2*>(base + 2) = hi23;
    *reinterpret_cast<__half2*>(base + 512) = lo01; *reinterpret_cast<__half2*>(base + 514) = lo23;
    *reinterpret_cast<__half2*>(base + 1024) = hi01; *reinterpret_cast<__half2*>(base + 1026) = hi23;
}

// ================= K1w: build W2T[n][k] = {W_hi; W_hi; W_lo} ===========================
__global__ void __launch_bounds__(256) k1w_split(const float* __restrict__ W) {
    int k = blockIdx.x, n = threadIdx.x;
    int ks = (k < 512) ? k : (k < 1024 ? k - 512 : k - 1024);
    float w = W[(size_t)ks * OUTC + n];
    __half hi = __float2half_rn(w);
    __half val = (k < 1024) ? hi : __float2half_rn(w - __half2float(hi));
    g_W2T[(size_t)n * KSPLIT + k] = val;
}

// ---------------- common HMMA helpers ----------------
__device__ __forceinline__ uint32_t smem_u32(const void* p) {
    uint32_t a;
    asm("{ .reg .u64 t; cvta.to.shared.u64 t, %1; cvt.u32.u64 %0, t; }" : "=r"(a) : "l"(p));
    return a;
}
__device__ __forceinline__ void cp16(uint32_t s, const void* g) {
    asm volatile("cp.async.cg.shared.global [%0], [%1], 16;" :: "r"(s), "l"(g) : "memory");
}
__device__ __forceinline__ void cp_commit() { asm volatile("cp.async.commit_group;" ::: "memory"); }
__device__ __forceinline__ void cp_wait1()  { asm volatile("cp.async.wait_group 1;" ::: "memory"); }
__device__ __forceinline__ void cp_wait0()  { asm volatile("cp.async.wait_group 0;" ::: "memory"); }

__device__ __forceinline__ void ldsm4(uint32_t* r, uint32_t addr) {
    asm volatile("ldmatrix.sync.aligned.m8n8.x4.shared.b16 {%0,%1,%2,%3}, [%4];"
                 : "=r"(r[0]), "=r"(r[1]), "=r"(r[2]), "=r"(r[3]) : "r"(addr));
}
__device__ __forceinline__ void hmma16816(float* c, const uint32_t* a, const uint32_t* b) {
    asm volatile("mma.sync.aligned.m16n8k16.row.col.f32.f16.f16.f32 "
                 "{%0,%1,%2,%3}, {%4,%5,%6,%7}, {%8,%9}, {%0,%1,%2,%3};"
                 : "+f"(c[0]), "+f"(c[1]), "+f"(c[2]), "+f"(c[3])
                 : "r"(a[0]), "r"(a[1]), "r"(a[2]), "r"(a[3]), "r"(b[0]), "r"(b[1]));
}

// ===== shared GEMM geometry: BM=128, BN=128, BK=64, 256 thr (8 warps 2m x 4n, 64x32) ===
#define V_ROWB 144
#define V_A_BYTES (128 * V_ROWB)                 // 18432
#define V_B_BYTES (128 * V_ROWB)                 // 18432
#define V_STAGE (V_A_BYTES + V_B_BYTES)          // 36864
#define V_SMEM_TOT (3 * V_STAGE)                 // 110592  -> 2 CTAs/SM

template <int STRIDE>
__device__ __forceinline__ void v_load(uint32_t stageBase, const __half* Asrc, const __half* Bsrc,
                                       int k0, int t) {
    #pragma unroll
    for (int q = 0; q < 4; q++) {
        int idx = t + q * 256;
        int r = idx >> 3, c = idx & 7;
        cp16(stageBase + r * V_ROWB + c * 16, Asrc + (size_t)r * STRIDE + k0 + c * 8);
    }
    #pragma unroll
    for (int q = 0; q < 4; q++) {
        int idx = t + q * 256;
        int n = idx >> 3, c = idx & 7;
        cp16(stageBase + V_A_BYTES + n * V_ROWB + c * 16, Bsrc + (size_t)n * STRIDE + k0 + c * 8);
    }
}

#define V_MAINLOOP(NK, ASRC, BSRC, STRIDE)                                                  \
    v_load<STRIDE>(sbase,           ASRC, BSRC, 0,  t); cp_commit();                        \
    v_load<STRIDE>(sbase + V_STAGE, ASRC, BSRC, 64, t); cp_commit();                        \
    for (int kc = 0; kc < (NK); kc++) {                                                     \
        if (kc >= (NK) - 2) cp_wait0(); else cp_wait1();                                    \
        __syncthreads();                                                                    \
        if (kc + 2 < (NK)) {                                                                \
            v_load<STRIDE>(sbase + ((kc + 2) % 3) * V_STAGE, ASRC, BSRC, (kc + 2) * 64, t); \
            cp_commit();                                                                    \
        }                                                                                   \
        uint32_t aT = sbase + (kc % 3) * V_STAGE;                                           \
        uint32_t bT = aT + V_A_BYTES;                                                       \
        _Pragma("unroll")                                                                   \
        for (int ks = 0; ks < 4; ks++) {                                                    \
            int ksb = ks * 32;                                                              \
            uint32_t afr[4][4], bfr[2][4];                                                  \
            _Pragma("unroll")                                                               \
            for (int mi = 0; mi < 4; mi++)                                                  \
                ldsm4(afr[mi], aT + (m0 + mi * 16 + aRowOff) * V_ROWB + ksb + aByte);       \
            _Pragma("unroll")                                                               \
            for (int pi = 0; pi < 2; pi++)                                                  \
                ldsm4(bfr[pi], bT + (n0 + pi * 16 + bRowOff) * V_ROWB + ksb + bByte);       \
            _Pragma("unroll")                                                               \
            for (int mi = 0; mi < 4; mi++)                                                  \
                _Pragma("unroll")                                                           \
                for (int ni = 0; ni < 4; ni++)                                              \
                    hmma16816(acc[mi][ni], afr[mi], &bfr[ni >> 1][(ni & 1) * 2]);           \
        }                                                                                   \
    }

// ================= K1b: Wh = h2 @ W2T^T (k4 geometry) + fused epilogues ================
__global__ void __launch_bounds__(256, 2) k1b_gemm(const float* __restrict__ a) {
    extern __shared__ char smem[];
    uint32_t sbase = smem_u32(smem);
    int t = threadIdx.x, wid = t >> 5, l = t & 31;
    int rowBase = blockIdx.x * 128;
    int colBase = blockIdx.y * 128;
    int m0 = (wid >> 2) * 64, n0 = (wid & 3) * 32;

    float acc[4][4][4];
    #pragma unroll
    for (int mi = 0; mi < 4; mi++)
        #pragma unroll
        for (int ni = 0; ni < 4; ni++)
            #pragma unroll
            for (int c = 0; c < 4; c++) acc[mi][ni][c] = 0.f;

    int sub = l >> 3, lr = l & 7;
    int aRowOff = (sub & 1) * 8 + lr, aByte = (sub >> 1) * 16;
    int bRowOff = ((sub >> 1) & 1) * 8 + lr, bByte = (sub & 1) * 16;

    const __half* Asrc = g_h2 + (size_t)rowBase * KSPLIT;
    const __half* Bsrc = g_W2T + (size_t)colBase * KSPLIT;
    V_MAINLOOP(KSPLIT / 64, Asrc, Bsrc, KSPLIT)

    // epilogue 1: WhT (fp16, transposed) from acc
    #pragma unroll
    for (int mi = 0; mi < 4; mi++)
        #pragma unroll
        for (int hh = 0; hh < 2; hh++) {
            int row = rowBase + m0 + mi * 16 + hh * 8 + (l >> 2);
            #pragma unroll
            for (int ni = 0; ni < 4; ni++)
                #pragma unroll
                for (int q = 0; q < 2; q++) {
                    int col = colBase + n0 + ni * 8 + (l & 3) * 2 + q;
                    g_WhT[(size_t)col * N_NODES + row] = __float2half(acc[mi][ni][hh * 2 + q]);
                }
        }

    // epilogue 2: per-CTA partial Wh1/Wh2 dots
    float a1c[8], a2c[8];
    #pragma unroll
    for (int ni = 0; ni < 4; ni++)
        #pragma unroll
        for (int q = 0; q < 2; q++) {
            int col = colBase + n0 + ni * 8 + (l & 3) * 2 + q;
            a1c[ni * 2 + q] = a[col];
            a2c[ni * 2 + q] = a[OUTC + col];
        }
    float s1p[8], s2p[8];
    #pragma unroll
    for (int mi = 0; mi < 4; mi++)
        #pragma unroll
        for (int hh = 0; hh < 2; hh++) {
            float s1 = 0.f, s2 = 0.f;
            #pragma unroll
            for (int ni = 0; ni < 4; ni++)
                #pragma unroll
                for (int q = 0; q < 2; q++) {
                    float v = acc[mi][ni][hh * 2 + q];
                    s1 += v * a1c[ni * 2 + q];
                    s2 += v * a2c[ni * 2 + q];
                }
            s1p[mi * 2 + hh] = s1; s2p[mi * 2 + hh] = s2;
        }
    #pragma unroll
    for (int idx = 0; idx < 8; idx++) {
        s1p[idx] += __shfl_xor_sync(0xffffffff, s1p[idx], 1);
        s1p[idx] += __shfl_xor_sync(0xffffffff, s1p[idx], 2);
        s2p[idx] += __shfl_xor_sync(0xffffffff, s2p[idx], 1);
        s2p[idx] += __shfl_xor_sync(0xffffffff, s2p[idx], 2);
    }
    float* red = reinterpret_cast<float*>(smem);
    __syncthreads();
    if ((l & 3) == 0) {
        #pragma unroll
        for (int mi = 0; mi < 4; mi++)
            #pragma unroll
            for (int hh = 0; hh < 2; hh++) {
                int row = m0 + mi * 16 + hh * 8 + (l >> 2);
                red[(row * 4 + (wid & 3)) * 2 + 0] = s1p[mi * 2 + hh];
                red[(row * 4 + (wid & 3)) * 2 + 1] = s2p[mi * 2 + hh];
            }
    }
    __syncthreads();
    if (t < 128) {
        float s1 = 0.f, s2 = 0.f;
        #pragma unroll
        for (int w = 0; w < 4; w++) { s1 += red[(t * 4 + w) * 2]; s2 += red[(t * 4 + w) * 2 + 1]; }
        g_pd[0][blockIdx.y][rowBase + t] = s1;
        g_pd[1][blockIdx.y][rowBase + t] = s2;
    }
}

// ================= K1c: combine dot partials, write Wh1/Wh2, global max ================
__global__ void __launch_bounds__(256) k1c_combine() {
    int r = blockIdx.x * 256 + threadIdx.x;
    float s1 = g_pd[0][0][r] + g_pd[0][1][r];
    float s2 = g_pd[1][0][r] + g_pd[1][1][r];
    g_Wh1[r] = s1;
    g_Wh2[r] = s2;
    float m = s2;
    #pragma unroll
    for (int o = 16; o > 0; o >>= 1) m = fmaxf(m, __shfl_xor_sync(0xffffffff, m, o));
    if ((threadIdx.x & 31) == 0) atomicMax(&g_gmax2u, fkey(m));
}

// ================= K3b: masked exp + row sum from packed bits (P fp16) =================
// thread t of row-block i handles word t: j = t*32 .. t*32+31 (contiguous 64B P write)
__global__ void __launch_bounds__(256) k3b_softmax() {
    __shared__ float red[256];
    int i = blockIdx.x, t = threadIdx.x;
    float wh1 = g_Wh1[i];
    float xB = wh1 + funkey(g_gmax2u);
    float B = xB > 0.f ? xB : ALPHA * xB;
    uint32_t word = g_bits[i * 256 + t];
    const float4* w2p = reinterpret_cast<const float4*>(g_Wh2 + t * 32);
    float s = 0.f;
    uint32_t pkw[16];
    #pragma unroll
    for (int g8 = 0; g8 < 8; g8++) {              // 4 j's per group
        float4 wv = w2p[g8];
        float ww[4] = {wv.x, wv.y, wv.z, wv.w};
        float p[4];
        #pragma unroll
        for (int q = 0; q < 4; q++) {
            float x = wh1 + ww[q];
            float e = fmaxf(x, ALPHA * x);        // leaky-relu, alpha<1
            float pe = __expf(e - B);
            p[q] = ((word >> (g8 * 4 + q)) & 1u) ? pe : 0.f;
        }
        __half h0 = __float2half(p[0]), h1 = __float2half(p[1]);
        __half h2 = __float2half(p[2]), h3 = __float2half(p[3]);
        s += __half2float(h0) + __half2float(h1) + __half2float(h2) + __half2float(h3);
        __half2 v0 = __halves2half2(h0, h1), v1 = __halves2half2(h2, h3);
        pkw[g8 * 2 + 0] = *reinterpret_cast<uint32_t*>(&v0);
        pkw[g8 * 2 + 1] = *reinterpret_cast<uint32_t*>(&v1);
    }
    uint4* dst = reinterpret_cast<uint4*>(g_P + (size_t)i * N_NODES + t * 32);
    __stcs(dst + 0, make_uint4(pkw[0],  pkw[1],  pkw[2],  pkw[3]));
    __stcs(dst + 1, make_uint4(pkw[4],  pkw[5],  pkw[6],  pkw[7]));
    __stcs(dst + 2, make_uint4(pkw[8],  pkw[9],  pkw[10], pkw[11]));
    __stcs(dst + 3, make_uint4(pkw[12], pkw[13], pkw[14], pkw[15]));

    red[t] = s; __syncthreads();
    for (int o = 128; o > 0; o >>= 1) { if (t < o) red[t] += red[t + o]; __syncthreads(); }
    if (t == 0) g_srow[i] = red[0];
}

// ===== K4: partial = P @ WhT^T, k-split 2.  BM=128, BN=128, BK=64, 256 thr, 2 CTA/SM ===
#define V_KHALF (N_NODES / 2)                    // 4096

__global__ void __launch_bounds__(256, 2) k4_gemm() {
    extern __shared__ char smem[];
    uint32_t sbase = smem_u32(smem);
    int t = threadIdx.x, wid = t >> 5, l = t & 31;
    int rowBase = blockIdx.x * 128;
    int colBase = blockIdx.y * 128;
    int khalf = blockIdx.z;
    int kbase = khalf * V_KHALF;
    int m0 = (wid >> 2) * 64, n0 = (wid & 3) * 32;

    float acc[4][4][4];
    #pragma unroll
    for (int mi = 0; mi < 4; mi++)
        #pragma unroll
        for (int ni = 0; ni < 4; ni++)
            #pragma unroll
            for (int c = 0; c < 4; c++) acc[mi][ni][c] = 0.f;

    int sub = l >> 3, lr = l & 7;
    int aRowOff = (sub & 1) * 8 + lr, aByte = (sub >> 1) * 16;
    int bRowOff = ((sub >> 1) & 1) * 8 + lr, bByte = (sub & 1) * 16;

    const __half* Asrc = g_P + (size_t)rowBase * N_NODES + kbase;
    const __half* Bsrc = g_WhT + (size_t)colBase * N_NODES + kbase;
    V_MAINLOOP(V_KHALF / 64, Asrc, Bsrc, N_NODES)

    float* dst = g_part[khalf];
    #pragma unroll
    for (int mi = 0; mi < 4; mi++)
        #pragma unroll
        for (int hh = 0; hh < 2; hh++) {
            int row = rowBase + m0 + mi * 16 + hh * 8 + (l >> 2);
            #pragma unroll
            for (int ni = 0; ni < 4; ni++) {
                int col = colBase + n0 + ni * 8 + (l & 3) * 2;
                float2 v = {acc[mi][ni][hh * 2], acc[mi][ni][hh * 2 + 1]};
                *reinterpret_cast<float2*>(dst + (size_t)row * OUTC + col) = v;
            }
        }
}

// ================= K5: out = relu((part0+part1)/s) ======================================
__global__ void __launch_bounds__(256) k5_combine(float* __restrict__ out) {
    int idx = blockIdx.x * 256 + threadIdx.x;
    int row = idx >> 6;
    float iv = 1.0f / g_srow[row];
    float4 p0 = *reinterpret_cast<const float4*>(&g_part[0][(size_t)idx * 4]);
    float4 p1 = *reinterpret_cast<const float4*>(&g_part[1][(size_t)idx * 4]);
    float4 v;
    v.x = fmaxf((p0.x + p1.x) * iv, 0.f);
    v.y = fmaxf((p0.y + p1.y) * iv, 0.f);
    v.z = fmaxf((p0.z + p1.z) * iv, 0.f);
    v.w = fmaxf((p0.w + p1.w) * iv, 0.f);
    *reinterpret_cast<float4*>(out + (size_t)idx * 4) = v;
}

// ================= launch =================
extern "C" void kernel_launch(void* const* d_in, const int* in_sizes, int n_in,
                              void* d_out, int out_size) {
    const float* h   = (const float*)d_in[0];
    const int*   adj = (const int*)d_in[1];
    const float* W   = (const float*)d_in[2];
    const float* a   = (const float*)d_in[3];
    float* out = (float*)d_out;

    static bool attr_set = false;
    if (!attr_set) {
        cudaFuncSetAttribute(k1b_gemm, cudaFuncAttributeMaxDynamicSharedMemorySize, V_SMEM_TOT);
        cudaFuncSetAttribute(k4_gemm,  cudaFuncAttributeMaxDynamicSharedMemorySize, V_SMEM_TOT);
        attr_set = true;
    }

    // fork: k0 (DRAM-bound adj pack) runs concurrently with the k1 tensor stack
    cudaEventRecord(g_res.evFork, 0);
    cudaStreamWaitEvent(g_res.s0, g_res.evFork, 0);
    k0_pack<<<N_NODES, 256, 0, g_res.s0>>>(adj);
    cudaEventRecord(g_res.evK0, g_res.s0);

    k1a_split<<<N_NODES * INC / 4 / 256, 256>>>(h);
    k1w_split<<<KSPLIT, 256>>>(W);
    k1b_gemm<<<dim3(N_NODES / 128, OUTC / 128), 256, V_SMEM_TOT>>>(a);
    k1c_combine<<<N_NODES / 256, 256>>>();

    // join: k3b needs the packed bits
    cudaStreamWaitEvent(0, g_res.evK0, 0);
    k3b_softmax<<<N_NODES, 256>>>();
    k4_gemm<<<dim3(N_NODES / 128, OUTC / 128, 2), 256, V_SMEM_TOT>>>();
    k5_combine<<<N_NODES * OUTC / 4 / 256, 256>>>(out);
}

// round 16
// speedup vs baseline: 1.1141x; 1.1141x over previous
#include <cuda_runtime.h>
#include <cuda_fp16.h>
#include <cstdint>

#define N_NODES 8192
#define INC 512
#define OUTC 256
#define ALPHA 0.5f
#define KSPLIT 1536                       // 3*INC for split-fp16 K1

// ---------------- scratch (device globals; no allocations allowed) ----------------
__device__ __half   g_WhT [OUTC * N_NODES];              // 4 MB fp16 Wh^T (K-major [n][k])
__device__ float    g_Wh1 [N_NODES];
__device__ float    g_Wh2 [N_NODES];
__device__ unsigned g_gmax2u;                            // max(Wh2) monotone uint key
__device__ float    g_srow[N_NODES];                     // softmax denominators
__device__ __half   g_h2  [(size_t)N_NODES * KSPLIT];    // 25 MB  [h_hi | h_lo | h_hi]
__device__ __half   g_W2T [OUTC * KSPLIT];               // 768 KB [n][k] = {W_hi;W_hi;W_lo}
__device__ __half   g_P   [(size_t)N_NODES * N_NODES];   // 128 MB unnormalized attention
__device__ float    g_part[2][N_NODES * OUTC];           // 16 MB k-split partials
__device__ float    g_pd  [2][2][N_NODES];               // [s1/s2][colCTA][row] dot partials
__device__ uint32_t g_bits[N_NODES * (N_NODES / 32)];    // 8 MB packed adj [row][word]

// ---- stream/events for k0 || k1-stack overlap; created at static-init ----
struct OverlapRes {
    cudaStream_t s0;
    cudaEvent_t  evFork, evK0;
    OverlapRes() {
        cudaStreamCreateWithFlags(&s0, cudaStreamNonBlocking);
        cudaEventCreateWithFlags(&evFork, cudaEventDisableTiming);
        cudaEventCreateWithFlags(&evK0,   cudaEventDisableTiming);
    }
};
static OverlapRes g_res;

__device__ __forceinline__ unsigned fkey(float x) {
    unsigned b = __float_as_uint(x);
    return (b & 0x80000000u) ? ~b : (b | 0x80000000u);
}
__device__ __forceinline__ float funkey(unsigned u) {
    unsigned b = (u & 0x80000000u) ? (u & 0x7FFFFFFFu) : ~u;
    return __uint_as_float(b);
}

// ================= K0: pack adj -> row-major bitmask g_bits[i][w] ======================
__global__ void __launch_bounds__(256) k0_pack(const int* __restrict__ adj) {
    int i = blockIdx.x;
    int t = threadIdx.x, wi = t >> 5, lane = t & 31;
    const int* row = adj + (size_t)i * N_NODES;
    #pragma unroll 8
    for (int k = 0; k < 32; k++) {
        int w = k * 8 + wi;
        int v = __ldcs(&row[w * 32 + lane]);
        unsigned m = __ballot_sync(0xffffffff, v > 0);
        if (lane == 0) g_bits[i * 256 + w] = m;
    }
}

// ================= K1a: split h -> [h_hi | h_lo | h_hi] fp16 ===========================
__global__ void __launch_bounds__(256) k1a_split(const float* __restrict__ hsrc) {
    if (blockIdx.x == 0 && threadIdx.x == 0) g_gmax2u = 0u;
    int idx = blockIdx.x * 256 + threadIdx.x;
    int i = idx >> 7, q = idx & 127;
    float4 v = *reinterpret_cast<const float4*>(hsrc + (size_t)idx * 4);
    __half hx = __float2half_rn(v.x), hy = __float2half_rn(v.y);
    __half hz = __float2half_rn(v.z), hw = __float2half_rn(v.w);
    __half lx = __float2half_rn(v.x - __half2float(hx));
    __half ly = __float2half_rn(v.y - __half2float(hy));
    __half lz = __float2half_rn(v.z - __half2float(hz));
    __half lw = __float2half_rn(v.w - __half2float(hw));
    __half2 hi01 = __halves2half2(hx, hy), hi23 = __halves2half2(hz, hw);
    __half2 lo01 = __halves2half2(lx, ly), lo23 = __halves2half2(lz, lw);
    __half* base = g_h2 + (size_t)i * KSPLIT + q * 4;
    *reinterpret_cast<__half2*>(base + 0) = hi01; *reinterpret_cast<__half2*>(base + 2) = hi23;
    *reinterpret_cast<__half2*>(base + 512) = lo01; *reinterpret_cast<__half2*>(base + 514) = lo23;
    *reinterpret_cast<__half2*>(base + 1024) = hi01; *reinterpret_cast<__half2*>(base + 1026) = hi23;
}

// ================= K1w: build W2T[n][k] = {W_hi; W_hi; W_lo} ===========================
__global__ void __launch_bounds__(256) k1w_split(const float* __restrict__ W) {
    int k = blockIdx.x, n = threadIdx.x;
    int ks = (k < 512) ? k : (k < 1024 ? k - 512 : k - 1024);
    float w = W[(size_t)ks * OUTC + n];
    __half hi = __float2half_rn(w);
    __half val = (k < 1024) ? hi : __float2half_rn(w - __half2float(hi));
    g_W2T[(size_t)n * KSPLIT + k] = val;
}

// ---------------- common HMMA helpers ----------------
__device__ __forceinline__ uint32_t smem_u32(const void* p) {
    uint32_t a;
    asm("{ .reg .u64 t; cvta.to.shared.u64 t, %1; cvt.u32.u64 %0, t; }" : "=r"(a) : "l"(p));
    return a;
}
__device__ __forceinline__ void cp16(uint32_t s, const void* g) {
    asm volatile("cp.async.cg.shared.global [%0], [%1], 16;" :: "r"(s), "l"(g) : "memory");
}
__device__ __forceinline__ void cp_commit() { asm volatile("cp.async.commit_group;" ::: "memory"); }
__device__ __forceinline__ void cp_wait1()  { asm volatile("cp.async.wait_group 1;" ::: "memory"); }
__device__ __forceinline__ void cp_wait0()  { asm volatile("cp.async.wait_group 0;" ::: "memory"); }

__device__ __forceinline__ void ldsm4(uint32_t* r, uint32_t addr) {
    asm volatile("ldmatrix.sync.aligned.m8n8.x4.shared.b16 {%0,%1,%2,%3}, [%4];"
                 : "=r"(r[0]), "=r"(r[1]), "=r"(r[2]), "=r"(r[3]) : "r"(addr));
}
__device__ __forceinline__ void hmma16816(float* c, const uint32_t* a, const uint32_t* b) {
    asm volatile("mma.sync.aligned.m16n8k16.row.col.f32.f16.f16.f32 "
                 "{%0,%1,%2,%3}, {%4,%5,%6,%7}, {%8,%9}, {%0,%1,%2,%3};"
                 : "+f"(c[0]), "+f"(c[1]), "+f"(c[2]), "+f"(c[3])
                 : "r"(a[0]), "r"(a[1]), "r"(a[2]), "r"(a[3]), "r"(b[0]), "r"(b[1]));
}

// ===== shared GEMM geometry: BM=128, BN=128, BK=64, 256 thr (8 warps 2m x 4n, 64x32) ===
#define V_ROWB 144
#define V_A_BYTES (128 * V_ROWB)                 // 18432
#define V_B_BYTES (128 * V_ROWB)                 // 18432
#define V_STAGE (V_A_BYTES + V_B_BYTES)          // 36864
#define V_SMEM_TOT (3 * V_STAGE)                 // 110592  -> 2 CTAs/SM

template <int STRIDE>
__device__ __forceinline__ void v_load(uint32_t stageBase, const __half* Asrc, const __half* Bsrc,
                                       int k0, int t) {
    #pragma unroll
    for (int q = 0; q < 4; q++) {
        int idx = t + q * 256;
        int r = idx >> 3, c = idx & 7;
        cp16(stageBase + r * V_ROWB + c * 16, Asrc + (size_t)r * STRIDE + k0 + c * 8);
    }
    #pragma unroll
    for (int q = 0; q < 4; q++) {
        int idx = t + q * 256;
        int n = idx >> 3, c = idx & 7;
        cp16(stageBase + V_A_BYTES + n * V_ROWB + c * 16, Bsrc + (size_t)n * STRIDE + k0 + c * 8);
    }
}

#define V_MAINLOOP(NK, ASRC, BSRC, STRIDE)                                                  \
    v_load<STRIDE>(sbase,           ASRC, BSRC, 0,  t); cp_commit();                        \
    v_load<STRIDE>(sbase + V_STAGE, ASRC, BSRC, 64, t); cp_commit();                        \
    for (int kc = 0; kc < (NK); kc++) {                                                     \
        if (kc >= (NK) - 2) cp_wait0(); else cp_wait1();                                    \
        __syncthreads();                                                                    \
        if (kc + 2 < (NK)) {                                                                \
            v_load<STRIDE>(sbase + ((kc + 2) % 3) * V_STAGE, ASRC, BSRC, (kc + 2) * 64, t); \
            cp_commit();                                                                    \
        }                                                                                   \
        uint32_t aT = sbase + (kc % 3) * V_STAGE;                                           \
        uint32_t bT = aT + V_A_BYTES;                                                       \
        _Pragma("unroll")                                                                   \
        for (int ks = 0; ks < 4; ks++) {                                                    \
            int ksb = ks * 32;                                                              \
            uint32_t afr[4][4], bfr[2][4];                                                  \
            _Pragma("unroll")                                                               \
            for (int mi = 0; mi < 4; mi++)                                                  \
                ldsm4(afr[mi], aT + (m0 + mi * 16 + aRowOff) * V_ROWB + ksb + aByte);       \
            _Pragma("unroll")                                                               \
            for (int pi = 0; pi < 2; pi++)                                                  \
                ldsm4(bfr[pi], bT + (n0 + pi * 16 + bRowOff) * V_ROWB + ksb + bByte);       \
            _Pragma("unroll")                                                               \
            for (int mi = 0; mi < 4; mi++)                                                  \
                _Pragma("unroll")                                                           \
                for (int ni = 0; ni < 4; ni++)                                              \
                    hmma16816(acc[mi][ni], afr[mi], &bfr[ni >> 1][(ni & 1) * 2]);           \
        }                                                                                   \
    }

// ================= K1b: Wh = h2 @ W2T^T (k4 geometry) + fused epilogues ================
__global__ void __launch_bounds__(256, 2) k1b_gemm(const float* __restrict__ a) {
    extern __shared__ char smem[];
    uint32_t sbase = smem_u32(smem);
    int t = threadIdx.x, wid = t >> 5, l = t & 31;
    int rowBase = blockIdx.x * 128;
    int colBase = blockIdx.y * 128;
    int m0 = (wid >> 2) * 64, n0 = (wid & 3) * 32;

    float acc[4][4][4];
    #pragma unroll
    for (int mi = 0; mi < 4; mi++)
        #pragma unroll
        for (int ni = 0; ni < 4; ni++)
            #pragma unroll
            for (int c = 0; c < 4; c++) acc[mi][ni][c] = 0.f;

    int sub = l >> 3, lr = l & 7;
    int aRowOff = (sub & 1) * 8 + lr, aByte = (sub >> 1) * 16;
    int bRowOff = ((sub >> 1) & 1) * 8 + lr, bByte = (sub & 1) * 16;

    const __half* Asrc = g_h2 + (size_t)rowBase * KSPLIT;
    const __half* Bsrc = g_W2T + (size_t)colBase * KSPLIT;
    V_MAINLOOP(KSPLIT / 64, Asrc, Bsrc, KSPLIT)

    // epilogue 1: WhT (fp16, transposed) from acc
    #pragma unroll
    for (int mi = 0; mi < 4; mi++)
        #pragma unroll
        for (int hh = 0; hh < 2; hh++) {
            int row = rowBase + m0 + mi * 16 + hh * 8 + (l >> 2);
            #pragma unroll
            for (int ni = 0; ni < 4; ni++)
                #pragma unroll
                for (int q = 0; q < 2; q++) {
                    int col = colBase + n0 + ni * 8 + (l & 3) * 2 + q;
                    g_WhT[(size_t)col * N_NODES + row] = __float2half(acc[mi][ni][hh * 2 + q]);
                }
        }

    // epilogue 2: per-CTA partial Wh1/Wh2 dots
    float a1c[8], a2c[8];
    #pragma unroll
    for (int ni = 0; ni < 4; ni++)
        #pragma unroll
        for (int q = 0; q < 2; q++) {
            int col = colBase + n0 + ni * 8 + (l & 3) * 2 + q;
            a1c[ni * 2 + q] = a[col];
            a2c[ni * 2 + q] = a[OUTC + col];
        }
    float s1p[8], s2p[8];
    #pragma unroll
    for (int mi = 0; mi < 4; mi++)
        #pragma unroll
        for (int hh = 0; hh < 2; hh++) {
            float s1 = 0.f, s2 = 0.f;
            #pragma unroll
            for (int ni = 0; ni < 4; ni++)
                #pragma unroll
                for (int q = 0; q < 2; q++) {
                    float v = acc[mi][ni][hh * 2 + q];
                    s1 += v * a1c[ni * 2 + q];
                    s2 += v * a2c[ni * 2 + q];
                }
            s1p[mi * 2 + hh] = s1; s2p[mi * 2 + hh] = s2;
        }
    #pragma unroll
    for (int idx = 0; idx < 8; idx++) {
        s1p[idx] += __shfl_xor_sync(0xffffffff, s1p[idx], 1);
        s1p[idx] += __shfl_xor_sync(0xffffffff, s1p[idx], 2);
        s2p[idx] += __shfl_xor_sync(0xffffffff, s2p[idx], 1);
        s2p[idx] += __shfl_xor_sync(0xffffffff, s2p[idx], 2);
    }
    float* red = reinterpret_cast<float*>(smem);
    __syncthreads();
    if ((l & 3) == 0) {
        #pragma unroll
        for (int mi = 0; mi < 4; mi++)
            #pragma unroll
            for (int hh = 0; hh < 2; hh++) {
                int row = m0 + mi * 16 + hh * 8 + (l >> 2);
                red[(row * 4 + (wid & 3)) * 2 + 0] = s1p[mi * 2 + hh];
                red[(row * 4 + (wid & 3)) * 2 + 1] = s2p[mi * 2 + hh];
            }
    }
    __syncthreads();
    if (t < 128) {
        float s1 = 0.f, s2 = 0.f;
        #pragma unroll
        for (int w = 0; w < 4; w++) { s1 += red[(t * 4 + w) * 2]; s2 += red[(t * 4 + w) * 2 + 1]; }
        g_pd[0][blockIdx.y][rowBase + t] = s1;
        g_pd[1][blockIdx.y][rowBase + t] = s2;
    }
}

// ================= K1c: combine dot partials, write Wh1/Wh2, global max ================
__global__ void __launch_bounds__(256) k1c_combine() {
    int r = blockIdx.x * 256 + threadIdx.x;
    float s1 = g_pd[0][0][r] + g_pd[0][1][r];
    float s2 = g_pd[1][0][r] + g_pd[1][1][r];
    g_Wh1[r] = s1;
    g_Wh2[r] = s2;
    float m = s2;
    #pragma unroll
    for (int o = 16; o > 0; o >>= 1) m = fmaxf(m, __shfl_xor_sync(0xffffffff, m, o));
    if ((threadIdx.x & 31) == 0) atomicMax(&g_gmax2u, fkey(m));
}

// ================= K3b: masked exp + row sum from packed bits (P fp16) =================
// COALESCED: thread tid handles float4 j4 = tid, tid+256, ... (consecutive across warp);
// 4 mask bits come from word j4>>3 (8 threads broadcast-read one 4B word).
__global__ void __launch_bounds__(256) k3b_softmax() {
    __shared__ float red[256];
    int i = blockIdx.x, tid = threadIdx.x;
    float wh1 = g_Wh1[i];
    float xB = wh1 + funkey(g_gmax2u);
    float B = xB > 0.f ? xB : ALPHA * xB;
    const uint32_t* bitsRow = g_bits + i * 256;
    const float4* w2p = reinterpret_cast<const float4*>(g_Wh2);
    float s = 0.f;
    #pragma unroll 4
    for (int j4 = tid; j4 < N_NODES / 4; j4 += 256) {
        uint32_t word = bitsRow[j4 >> 3];
        int sh = (j4 & 7) * 4;
        float4 w2 = w2p[j4];
        float x0 = wh1 + w2.x, x1 = wh1 + w2.y, x2 = wh1 + w2.z, x3 = wh1 + w2.w;
        float e0 = fmaxf(x0, ALPHA * x0);
        float e1 = fmaxf(x1, ALPHA * x1);
        float e2 = fmaxf(x2, ALPHA * x2);
        float e3 = fmaxf(x3, ALPHA * x3);
        float p0 = ((word >> (sh + 0)) & 1u) ? __expf(e0 - B) : 0.f;
        float p1 = ((word >> (sh + 1)) & 1u) ? __expf(e1 - B) : 0.f;
        float p2 = ((word >> (sh + 2)) & 1u) ? __expf(e2 - B) : 0.f;
        float p3 = ((word >> (sh + 3)) & 1u) ? __expf(e3 - B) : 0.f;
        __half h0 = __float2half(p0), h1 = __float2half(p1);
        __half h2 = __float2half(p2), h3 = __float2half(p3);
        s += __half2float(h0) + __half2float(h1) + __half2float(h2) + __half2float(h3);
        __half2 v0 = __halves2half2(h0, h1), v1 = __halves2half2(h2, h3);
        uint2 pk;
        pk.x = *reinterpret_cast<uint32_t*>(&v0);
        pk.y = *reinterpret_cast<uint32_t*>(&v1);
        __stcs(reinterpret_cast<uint2*>(g_P + (size_t)i * N_NODES + (size_t)j4 * 4), pk);
    }
    red[tid] = s; __syncthreads();
    for (int o = 128; o > 0; o >>= 1) { if (tid < o) red[tid] += red[tid + o]; __syncthreads(); }
    if (tid == 0) g_srow[i] = red[0];
}

// ===== K4: partial = P @ WhT^T, k-split 2.  BM=128, BN=128, BK=64, 256 thr, 2 CTA/SM ===
#define V_KHALF (N_NODES / 2)                    // 4096

__global__ void __launch_bounds__(256, 2) k4_gemm() {
    extern __shared__ char smem[];
    uint32_t sbase = smem_u32(smem);
    int t = threadIdx.x, wid = t >> 5, l = t & 31;
    int rowBase = blockIdx.x * 128;
    int colBase = blockIdx.y * 128;
    int khalf = blockIdx.z;
    int kbase = khalf * V_KHALF;
    int m0 = (wid >> 2) * 64, n0 = (wid & 3) * 32;

    float acc[4][4][4];
    #pragma unroll
    for (int mi = 0; mi < 4; mi++)
        #pragma unroll
        for (int ni = 0; ni < 4; ni++)
            #pragma unroll
            for (int c = 0; c < 4; c++) acc[mi][ni][c] = 0.f;

    int sub = l >> 3, lr = l & 7;
    int aRowOff = (sub & 1) * 8 + lr, aByte = (sub >> 1) * 16;
    int bRowOff = ((sub >> 1) & 1) * 8 + lr, bByte = (sub & 1) * 16;

    const __half* Asrc = g_P + (size_t)rowBase * N_NODES + kbase;
    const __half* Bsrc = g_WhT + (size_t)colBase * N_NODES + kbase;
    V_MAINLOOP(V_KHALF / 64, Asrc, Bsrc, N_NODES)

    float* dst = g_part[khalf];
    #pragma unroll
    for (int mi = 0; mi < 4; mi++)
        #pragma unroll
        for (int hh = 0; hh < 2; hh++) {
            int row = rowBase + m0 + mi * 16 + hh * 8 + (l >> 2);
            #pragma unroll
            for (int ni = 0; ni < 4; ni++) {
                int col = colBase + n0 + ni * 8 + (l & 3) * 2;
                float2 v = {acc[mi][ni][hh * 2], acc[mi][ni][hh * 2 + 1]};
                *reinterpret_cast<float2*>(dst + (size_t)row * OUTC + col) = v;
            }
        }
}

// ================= K5: out = relu((part0+part1)/s) ======================================
__global__ void __launch_bounds__(256) k5_combine(float* __restrict__ out) {
    int idx = blockIdx.x * 256 + threadIdx.x;
    int row = idx >> 6;
    float iv = 1.0f / g_srow[row];
    float4 p0 = *reinterpret_cast<const float4*>(&g_part[0][(size_t)idx * 4]);
    float4 p1 = *reinterpret_cast<const float4*>(&g_part[1][(size_t)idx * 4]);
    float4 v;
    v.x = fmaxf((p0.x + p1.x) * iv, 0.f);
    v.y = fmaxf((p0.y + p1.y) * iv, 0.f);
    v.z = fmaxf((p0.z + p1.z) * iv, 0.f);
    v.w = fmaxf((p0.w + p1.w) * iv, 0.f);
    *reinterpret_cast<float4*>(out + (size_t)idx * 4) = v;
}

// ================= launch =================
extern "C" void kernel_launch(void* const* d_in, const int* in_sizes, int n_in,
                              void* d_out, int out_size) {
    const float* h   = (const float*)d_in[0];
    const int*   adj = (const int*)d_in[1];
    const float* W   = (const float*)d_in[2];
    const float* a   = (const float*)d_in[3];
    float* out = (float*)d_out;

    static bool attr_set = false;
    if (!attr_set) {
        cudaFuncSetAttribute(k1b_gemm, cudaFuncAttributeMaxDynamicSharedMemorySize, V_SMEM_TOT);
        cudaFuncSetAttribute(k4_gemm,  cudaFuncAttributeMaxDynamicSharedMemorySize, V_SMEM_TOT);
        attr_set = true;
    }

    // fork: k0 (DRAM-bound adj pack) runs concurrently with the k1 tensor stack
    cudaEventRecord(g_res.evFork, 0);
    cudaStreamWaitEvent(g_res.s0, g_res.evFork, 0);
    k0_pack<<<N_NODES, 256, 0, g_res.s0>>>(adj);
    cudaEventRecord(g_res.evK0, g_res.s0);

    k1a_split<<<N_NODES * INC / 4 / 256, 256>>>(h);
    k1w_split<<<KSPLIT, 256>>>(W);
    k1b_gemm<<<dim3(N_NODES / 128, OUTC / 128), 256, V_SMEM_TOT>>>(a);
    k1c_combine<<<N_NODES / 256, 256>>>();

    // join: k3b needs the packed bits
    cudaStreamWaitEvent(0, g_res.evK0, 0);
    k3b_softmax<<<N_NODES, 256>>>();
    k4_gemm<<<dim3(N_NODES / 128, OUTC / 128, 2), 256, V_SMEM_TOT>>>();
    k5_combine<<<N_NODES * OUTC / 4 / 256, 256>>>(out);
}

// round 17
// speedup vs baseline: 1.4963x; 1.3431x over previous
#include <cuda_runtime.h>
#include <cuda_fp16.h>
#include <cstdint>

#define N_NODES 8192
#define INC 512
#define OUTC 256
#define ALPHA 0.5f
#define KSPLIT 1536                       // GEMM K for split-fp16 K1 (W side)
#define H2STRIDE 1024                     // g_h2 row length: [hi(512) | lo(512)]

// ---------------- scratch (device globals; no allocations allowed) ----------------
__device__ __half   g_WhT [OUTC * N_NODES];              // 4 MB fp16 Wh^T (K-major [n][k])
__device__ float    g_Wh1 [N_NODES];
__device__ float    g_Wh2 [N_NODES];
__device__ unsigned g_gmax2u;                            // max(Wh2) monotone uint key
__device__ float    g_srow[N_NODES];                     // softmax denominators
__device__ __half   g_h2  [(size_t)N_NODES * H2STRIDE];  // 16 MB  [h_hi | h_lo]
__device__ __half   g_W2T [OUTC * KSPLIT];               // 768 KB [n][k] = {W_hi;W_hi;W_lo}
__device__ __half   g_P   [(size_t)N_NODES * N_NODES];   // 128 MB unnormalized attention
__device__ float    g_part[2][N_NODES * OUTC];           // 16 MB k-split partials
__device__ float    g_pd  [2][2][N_NODES];               // [s1/s2][colCTA][row] dot partials

__device__ __forceinline__ unsigned fkey(float x) {
    unsigned b = __float_as_uint(x);
    return (b & 0x80000000u) ? ~b : (b | 0x80000000u);
}
__device__ __forceinline__ float funkey(unsigned u) {
    unsigned b = (u & 0x80000000u) ? (u & 0x7FFFFFFFu) : ~u;
    return __uint_as_float(b);
}

// ================= K1a: split h -> [h_hi | h_lo] fp16 ==================================
__global__ void __launch_bounds__(256) k1a_split(const float* __restrict__ hsrc) {
    if (blockIdx.x == 0 && threadIdx.x == 0) g_gmax2u = 0u;
    int idx = blockIdx.x * 256 + threadIdx.x;   // float4 index, 1M total
    int i = idx >> 7, q = idx & 127;
    float4 v = *reinterpret_cast<const float4*>(hsrc + (size_t)idx * 4);
    __half hx = __float2half_rn(v.x), hy = __float2half_rn(v.y);
    __half hz = __float2half_rn(v.z), hw = __float2half_rn(v.w);
    __half lx = __float2half_rn(v.x - __half2float(hx));
    __half ly = __float2half_rn(v.y - __half2float(hy));
    __half lz = __float2half_rn(v.z - __half2float(hz));
    __half lw = __float2half_rn(v.w - __half2float(hw));
    __half2 hi01 = __halves2half2(hx, hy), hi23 = __halves2half2(hz, hw);
    __half2 lo01 = __halves2half2(lx, ly), lo23 = __halves2half2(lz, lw);
    __half* base = g_h2 + (size_t)i * H2STRIDE + q * 4;
    *reinterpret_cast<__half2*>(base + 0) = hi01; *reinterpret_cast<__half2*>(base + 2) = hi23;
    *reinterpret_cast<__half2*>(base + 512) = lo01; *reinterpret_cast<__half2*>(base + 514) = lo23;
}

// ================= K1w: build W2T[n][k] = {W_hi; W_hi; W_lo} ===========================
__global__ void __launch_bounds__(256) k1w_split(const float* __restrict__ W) {
    int k = blockIdx.x, n = threadIdx.x;
    int ks = (k < 512) ? k : (k < 1024 ? k - 512 : k - 1024);
    float w = W[(size_t)ks * OUTC + n];
    __half hi = __float2half_rn(w);
    __half val = (k < 1024) ? hi : __float2half_rn(w - __half2float(hi));
    g_W2T[(size_t)n * KSPLIT + k] = val;
}

// ---------------- common HMMA helpers ----------------
__device__ __forceinline__ uint32_t smem_u32(const void* p) {
    uint32_t a;
    asm("{ .reg .u64 t; cvta.to.shared.u64 t, %1; cvt.u32.u64 %0, t; }" : "=r"(a) : "l"(p));
    return a;
}
__device__ __forceinline__ void cp16(uint32_t s, const void* g) {
    asm volatile("cp.async.cg.shared.global [%0], [%1], 16;" :: "r"(s), "l"(g) : "memory");
}
__device__ __forceinline__ void cp_commit() { asm volatile("cp.async.commit_group;" ::: "memory"); }
__device__ __forceinline__ void cp_wait1()  { asm volatile("cp.async.wait_group 1;" ::: "memory"); }
__device__ __forceinline__ void cp_wait0()  { asm volatile("cp.async.wait_group 0;" ::: "memory"); }

__device__ __forceinline__ void ldsm4(uint32_t* r, uint32_t addr) {
    asm volatile("ldmatrix.sync.aligned.m8n8.x4.shared.b16 {%0,%1,%2,%3}, [%4];"
                 : "=r"(r[0]), "=r"(r[1]), "=r"(r[2]), "=r"(r[3]) : "r"(addr));
}
__device__ __forceinline__ void hmma16816(float* c, const uint32_t* a, const uint32_t* b) {
    asm volatile("mma.sync.aligned.m16n8k16.row.col.f32.f16.f16.f32 "
                 "{%0,%1,%2,%3}, {%4,%5,%6,%7}, {%8,%9}, {%0,%1,%2,%3};"
                 : "+f"(c[0]), "+f"(c[1]), "+f"(c[2]), "+f"(c[3])
                 : "r"(a[0]), "r"(a[1]), "r"(a[2]), "r"(a[3]), "r"(b[0]), "r"(b[1]));
}

// ===== shared GEMM geometry: BM=128, BN=128, BK=64, 256 thr (8 warps 2m x 4n, 64x32) ===
#define V_ROWB 144
#define V_A_BYTES (128 * V_ROWB)                 // 18432
#define V_B_BYTES (128 * V_ROWB)                 // 18432
#define V_STAGE (V_A_BYTES + V_B_BYTES)          // 36864
#define V_SMEM_TOT (3 * V_STAGE)                 // 110592  -> 2 CTAs/SM

// WRAP_A: fold A k-index >= 1024 back onto the hi segment (k1b split-fp16 trick)
template <int STRIDE_A, int STRIDE_B, bool WRAP_A>
__device__ __forceinline__ void v_load(uint32_t stageBase, const __half* Asrc, const __half* Bsrc,
                                       int k0, int t) {
    int ka = (WRAP_A && k0 >= 1024) ? k0 - 1024 : k0;   // BK-aligned boundary: uniform per stage
    #pragma unroll
    for (int q = 0; q < 4; q++) {
        int idx = t + q * 256;
        int r = idx >> 3, c = idx & 7;
        cp16(stageBase + r * V_ROWB + c * 16, Asrc + (size_t)r * STRIDE_A + ka + c * 8);
    }
    #pragma unroll
    for (int q = 0; q < 4; q++) {
        int idx = t + q * 256;
        int n = idx >> 3, c = idx & 7;
        cp16(stageBase + V_A_BYTES + n * V_ROWB + c * 16, Bsrc + (size_t)n * STRIDE_B + k0 + c * 8);
    }
}

// inner compute: b-frags first, then interleave [ldsm a(mi) -> 4x HMMA(mi)]; single live a-frag
#define V_MAINLOOP(NK, ASRC, BSRC, STRA, STRB, WRAPA)                                       \
    v_load<STRA, STRB, WRAPA>(sbase,           ASRC, BSRC, 0,  t); cp_commit();             \
    v_load<STRA, STRB, WRAPA>(sbase + V_STAGE, ASRC, BSRC, 64, t); cp_commit();             \
    for (int kc = 0; kc < (NK); kc++) {                                                     \
        if (kc >= (NK) - 2) cp_wait0(); else cp_wait1();                                    \
        __syncthreads();                                                                    \
        if (kc + 2 < (NK)) {                                                                \
            v_load<STRA, STRB, WRAPA>(sbase + ((kc + 2) % 3) * V_STAGE, ASRC, BSRC,         \
                                      (kc + 2) * 64, t);                                    \
            cp_commit();                                                                    \
        }                                                                                   \
        uint32_t aT = sbase + (kc % 3) * V_STAGE;                                           \
        uint32_t bT = aT + V_A_BYTES;                                                       \
        _Pragma("unroll")                                                                   \
        for (int ks = 0; ks < 4; ks++) {                                                    \
            int ksb = ks * 32;                                                              \
            uint32_t bfr[2][4];                                                             \
            _Pragma("unroll")                                                               \
            for (int pi = 0; pi < 2; pi++)                                                  \
                ldsm4(bfr[pi], bT + (n0 + pi * 16 + bRowOff) * V_ROWB + ksb + bByte);       \
            _Pragma("unroll")                                                               \
            for (int mi = 0; mi < 4; mi++) {                                                \
                uint32_t afr[4];                                                            \
                ldsm4(afr, aT + (m0 + mi * 16 + aRowOff) * V_ROWB + ksb + aByte);           \
                _Pragma("unroll")                                                           \
                for (int ni = 0; ni < 4; ni++)                                              \
                    hmma16816(acc[mi][ni], afr, &bfr[ni >> 1][(ni & 1) * 2]);               \
            }                                                                               \
        }                                                                                   \
    }

// ================= K1b: Wh = h2 @ W2T^T (k4 geometry) + fused epilogues ================
__global__ void __launch_bounds__(256, 2) k1b_gemm(const float* __restrict__ a) {
    extern __shared__ char smem[];
    uint32_t sbase = smem_u32(smem);
    int t = threadIdx.x, wid = t >> 5, l = t & 31;
    int rowBase = blockIdx.x * 128;
    int colBase = blockIdx.y * 128;
    int m0 = (wid >> 2) * 64, n0 = (wid & 3) * 32;

    float acc[4][4][4];
    #pragma unroll
    for (int mi = 0; mi < 4; mi++)
        #pragma unroll
        for (int ni = 0; ni < 4; ni++)
            #pragma unroll
            for (int c = 0; c < 4; c++) acc[mi][ni][c] = 0.f;

    int sub = l >> 3, lr = l & 7;
    int aRowOff = (sub & 1) * 8 + lr, aByte = (sub >> 1) * 16;
    int bRowOff = ((sub >> 1) & 1) * 8 + lr, bByte = (sub & 1) * 16;

    const __half* Asrc = g_h2 + (size_t)rowBase * H2STRIDE;
    const __half* Bsrc = g_W2T + (size_t)colBase * KSPLIT;
    V_MAINLOOP(KSPLIT / 64, Asrc, Bsrc, H2STRIDE, KSPLIT, true)

    // epilogue 1: WhT (fp16, transposed) from acc
    #pragma unroll
    for (int mi = 0; mi < 4; mi++)
        #pragma unroll
        for (int hh = 0; hh < 2; hh++) {
            int row = rowBase + m0 + mi * 16 + hh * 8 + (l >> 2);
            #pragma unroll
            for (int ni = 0; ni < 4; ni++)
                #pragma unroll
                for (int q = 0; q < 2; q++) {
                    int col = colBase + n0 + ni * 8 + (l & 3) * 2 + q;
                    g_WhT[(size_t)col * N_NODES + row] = __float2half(acc[mi][ni][hh * 2 + q]);
                }
        }

    // epilogue 2: per-CTA partial Wh1/Wh2 dots
    float a1c[8], a2c[8];
    #pragma unroll
    for (int ni = 0; ni < 4; ni++)
        #pragma unroll
        for (int q = 0; q < 2; q++) {
            int col = colBase + n0 + ni * 8 + (l & 3) * 2 + q;
            a1c[ni * 2 + q] = a[col];
            a2c[ni * 2 + q] = a[OUTC + col];
        }
    float s1p[8], s2p[8];
    #pragma unroll
    for (int mi = 0; mi < 4; mi++)
        #pragma unroll
        for (int hh = 0; hh < 2; hh++) {
            float s1 = 0.f, s2 = 0.f;
            #pragma unroll
            for (int ni = 0; ni < 4; ni++)
                #pragma unroll
                for (int q = 0; q < 2; q++) {
                    float v = acc[mi][ni][hh * 2 + q];
                    s1 += v * a1c[ni * 2 + q];
                    s2 += v * a2c[ni * 2 + q];
                }
            s1p[mi * 2 + hh] = s1; s2p[mi * 2 + hh] = s2;
        }
    #pragma unroll
    for (int idx = 0; idx < 8; idx++) {
        s1p[idx] += __shfl_xor_sync(0xffffffff, s1p[idx], 1);
        s1p[idx] += __shfl_xor_sync(0xffffffff, s1p[idx], 2);
        s2p[idx] += __shfl_xor_sync(0xffffffff, s2p[idx], 1);
        s2p[idx] += __shfl_xor_sync(0xffffffff, s2p[idx], 2);
    }
    float* red = reinterpret_cast<float*>(smem);
    __syncthreads();
    if ((l & 3) == 0) {
        #pragma unroll
        for (int mi = 0; mi < 4; mi++)
            #pragma unroll
            for (int hh = 0; hh < 2; hh++) {
                int row = m0 + mi * 16 + hh * 8 + (l >> 2);
                red[(row * 4 + (wid & 3)) * 2 + 0] = s1p[mi * 2 + hh];
                red[(row * 4 + (wid & 3)) * 2 + 1] = s2p[mi * 2 + hh];
            }
    }
    __syncthreads();
    if (t < 128) {
        float s1 = 0.f, s2 = 0.f;
        #pragma unroll
        for (int w = 0; w < 4; w++) { s1 += red[(t * 4 + w) * 2]; s2 += red[(t * 4 + w) * 2 + 1]; }
        g_pd[0][blockIdx.y][rowBase + t] = s1;
        g_pd[1][blockIdx.y][rowBase + t] = s2;
    }
}

// ================= K1c: combine dot partials, write Wh1/Wh2, global max ================
__global__ void __launch_bounds__(256) k1c_combine() {
    int r = blockIdx.x * 256 + threadIdx.x;
    float s1 = g_pd[0][0][r] + g_pd[0][1][r];
    float s2 = g_pd[1][0][r] + g_pd[1][1][r];
    g_Wh1[r] = s1;
    g_Wh2[r] = s2;
    float m = s2;
    #pragma unroll
    for (int o = 16; o > 0; o >>= 1) m = fmaxf(m, __shfl_xor_sync(0xffffffff, m, o));
    if ((threadIdx.x & 31) == 0) atomicMax(&g_gmax2u, fkey(m));
}

// ================= K3: single-pass masked exp + row sum (P fp16) =================
__global__ void __launch_bounds__(256) k3_softmax(const int* __restrict__ adj) {
    __shared__ float red[256];
    int i = blockIdx.x, tid = threadIdx.x;
    float wh1 = g_Wh1[i];
    float xB = wh1 + funkey(g_gmax2u);
    float B = xB > 0.f ? xB : ALPHA * xB;
    const int4* arow = reinterpret_cast<const int4*>(adj + (size_t)i * N_NODES);
    const float4* w2p = reinterpret_cast<const float4*>(g_Wh2);
    float s = 0.f;
    #pragma unroll 4
    for (int j4 = tid; j4 < N_NODES / 4; j4 += 256) {
        int4 av = __ldcs(&arow[j4]);
        float4 w2 = w2p[j4];
        float x0 = wh1 + w2.x, x1 = wh1 + w2.y, x2 = wh1 + w2.z, x3 = wh1 + w2.w;
        float e0 = x0 > 0.f ? x0 : ALPHA * x0;
        float e1 = x1 > 0.f ? x1 : ALPHA * x1;
        float e2 = x2 > 0.f ? x2 : ALPHA * x2;
        float e3 = x3 > 0.f ? x3 : ALPHA * x3;
        float p0 = av.x > 0 ? __expf(e0 - B) : 0.f;
        float p1 = av.y > 0 ? __expf(e1 - B) : 0.f;
        float p2 = av.z > 0 ? __expf(e2 - B) : 0.f;
        float p3 = av.w > 0 ? __expf(e3 - B) : 0.f;
        __half h0 = __float2half(p0), h1 = __float2half(p1);
        __half h2 = __float2half(p2), h3 = __float2half(p3);
        s += __half2float(h0) + __half2float(h1) + __half2float(h2) + __half2float(h3);
        __half2 v0 = __halves2half2(h0, h1), v1 = __halves2half2(h2, h3);
        uint2 pk;
        pk.x = *reinterpret_cast<uint32_t*>(&v0);
        pk.y = *reinterpret_cast<uint32_t*>(&v1);
        __stcs(reinterpret_cast<uint2*>(g_P + (size_t)i * N_NODES + (size_t)j4 * 4), pk);
    }
    red[tid] = s; __syncthreads();
    for (int o = 128; o > 0; o >>= 1) { if (tid < o) red[tid] += red[tid + o]; __syncthreads(); }
    if (tid == 0) g_srow[i] = red[0];
}

// ===== K4: partial = P @ WhT^T, k-split 2.  BM=128, BN=128, BK=64, 256 thr, 2 CTA/SM ===
#define V_KHALF (N_NODES / 2)                    // 4096

__global__ void __launch_bounds__(256, 2) k4_gemm() {
    extern __shared__ char smem[];
    uint32_t sbase = smem_u32(smem);
    int t = threadIdx.x, wid = t >> 5, l = t & 31;
    int rowBase = blockIdx.x * 128;
    int colBase = blockIdx.y * 128;
    int khalf = blockIdx.z;
    int kbase = khalf * V_KHALF;
    int m0 = (wid >> 2) * 64, n0 = (wid & 3) * 32;

    float acc[4][4][4];
    #pragma unroll
    for (int mi = 0; mi < 4; mi++)
        #pragma unroll
        for (int ni = 0; ni < 4; ni++)
            #pragma unroll
            for (int c = 0; c < 4; c++) acc[mi][ni][c] = 0.f;

    int sub = l >> 3, lr = l & 7;
    int aRowOff = (sub & 1) * 8 + lr, aByte = (sub >> 1) * 16;
    int bRowOff = ((sub >> 1) & 1) * 8 + lr, bByte = (sub & 1) * 16;

    const __half* Asrc = g_P + (size_t)rowBase * N_NODES + kbase;
    const __half* Bsrc = g_WhT + (size_t)colBase * N_NODES + kbase;
    V_MAINLOOP(V_KHALF / 64, Asrc, Bsrc, N_NODES, N_NODES, false)

    float* dst = g_part[khalf];
    #pragma unroll
    for (int mi = 0; mi < 4; mi++)
        #pragma unroll
        for (int hh = 0; hh < 2; hh++) {
            int row = rowBase + m0 + mi * 16 + hh * 8 + (l >> 2);
            #pragma unroll
            for (int ni = 0; ni < 4; ni++) {
                int col = colBase + n0 + ni * 8 + (l & 3) * 2;
                float2 v = {acc[mi][ni][hh * 2], acc[mi][ni][hh * 2 + 1]};
                *reinterpret_cast<float2*>(dst + (size_t)row * OUTC + col) = v;
            }
        }
}

// ================= K5: out = relu((part0+part1)/s) ======================================
__global__ void __launch_bounds__(256) k5_combine(float* __restrict__ out) {
    int idx = blockIdx.x * 256 + threadIdx.x;
    int row = idx >> 6;
    float iv = 1.0f / g_srow[row];
    float4 p0 = *reinterpret_cast<const float4*>(&g_part[0][(size_t)idx * 4]);
    float4 p1 = *reinterpret_cast<const float4*>(&g_part[1][(size_t)idx * 4]);
    float4 v;
    v.x = fmaxf((p0.x + p1.x) * iv, 0.f);
    v.y = fmaxf((p0.y + p1.y) * iv, 0.f);
    v.z = fmaxf((p0.z + p1.z) * iv, 0.f);
    v.w = fmaxf((p0.w + p1.w) * iv, 0.f);
    *reinterpret_cast<float4*>(out + (size_t)idx * 4) = v;
}

// ================= launch =================
extern "C" void kernel_launch(void* const* d_in, const int* in_sizes, int n_in,
                              void* d_out, int out_size) {
    const float* h   = (const float*)d_in[0];
    const int*   adj = (const int*)d_in[1];
    const float* W   = (const float*)d_in[2];
    const float* a   = (const float*)d_in[3];
    float* out = (float*)d_out;

    static bool attr_set = false;
    if (!attr_set) {
        cudaFuncSetAttribute(k1b_gemm, cudaFuncAttributeMaxDynamicSharedMemorySize, V_SMEM_TOT);
        cudaFuncSetAttribute(k4_gemm,  cudaFuncAttributeMaxDynamicSharedMemorySize, V_SMEM_TOT);
        attr_set = true;
    }

    k1a_split<<<N_NODES * INC / 4 / 256, 256>>>(h);
    k1w_split<<<KSPLIT, 256>>>(W);
    k1b_gemm<<<dim3(N_NODES / 128, OUTC / 128), 256, V_SMEM_TOT>>>(a);
    k1c_combine<<<N_NODES / 256, 256>>>();
    k3_softmax<<<N_NODES, 256>>>(adj);
    k4_gemm<<<dim3(N_NODES / 128, OUTC / 128, 2), 256, V_SMEM_TOT>>>();
    k5_combine<<<N_NODES * OUTC / 4 / 256, 256>>>(out);
}